// round 1
// baseline (speedup 1.0000x reference)
#include <cuda_runtime.h>
#include <math.h>

#define Dn 4096
#define Bn 32
#define Un 64

// ---------------- scratch (__device__ globals; no allocation) ----------------
__device__ float g_act[2][Bn * Dn];      // [0]=stim_out, [1]=rec_out
__device__ float g_h1[Bn * 512];
__device__ float g_h2[Bn * 256];
__device__ float g_o[Bn * Un];
__device__ float g_alpha[Dn];
__device__ float g_norm[2][Dn];
__device__ float g_part[2][64][Dn];      // per-(matrix, j-block) row sumsq partials

// ---------------------------------------------------------------------------
// Forward GEMM: O = relu(X @ W),  X:[32,4096], W:[4096,4096]
// BM=32, BN=64, BK=32; 256 threads; thread micro-tile 2x4.
// blockIdx.y selects (stimulus,W_heb) vs (prev_act,W_rec).
// ---------------------------------------------------------------------------
__global__ __launch_bounds__(256) void fwd_gemm(
    const float* __restrict__ stim, const float* __restrict__ prev,
    const float* __restrict__ Wh, const float* __restrict__ Wr)
{
    const int mat = blockIdx.y;
    const float* __restrict__ X = mat ? prev : stim;
    const float* __restrict__ W = mat ? Wr : Wh;
    float* __restrict__ O = g_act[mat];
    const int n0 = blockIdx.x * 64;

    __shared__ float Xs[32][33];   // [k][m], padded
    __shared__ float Ws[32][64];   // [k][n]

    const int tid = threadIdx.x;
    const int tx = tid & 15;       // n-group (4 cols each)
    const int ty = tid >> 4;       // m-group (2 rows each)
    const int bld = tid >> 5;      // 0..7  (X load)
    const int kld = tid & 31;
    const int kw  = tid >> 4;      // 0..15 (W load)
    const int nw  = (tid & 15) << 2;

    float acc[2][4] = {};

    for (int k0 = 0; k0 < Dn; k0 += 32) {
        #pragma unroll
        for (int r = 0; r < 4; r++)
            Xs[kld][bld + 8 * r] = X[(bld + 8 * r) * Dn + k0 + kld];
        #pragma unroll
        for (int r = 0; r < 2; r++)
            *(float4*)&Ws[kw + 16 * r][nw] =
                *(const float4*)&W[(size_t)(k0 + kw + 16 * r) * Dn + n0 + nw];
        __syncthreads();

        #pragma unroll
        for (int kk = 0; kk < 32; kk++) {
            float a0 = Xs[kk][ty * 2 + 0];
            float a1 = Xs[kk][ty * 2 + 1];
            float4 bv = *(const float4*)&Ws[kk][tx * 4];
            acc[0][0] = fmaf(a0, bv.x, acc[0][0]);
            acc[0][1] = fmaf(a0, bv.y, acc[0][1]);
            acc[0][2] = fmaf(a0, bv.z, acc[0][2]);
            acc[0][3] = fmaf(a0, bv.w, acc[0][3]);
            acc[1][0] = fmaf(a1, bv.x, acc[1][0]);
            acc[1][1] = fmaf(a1, bv.y, acc[1][1]);
            acc[1][2] = fmaf(a1, bv.z, acc[1][2]);
            acc[1][3] = fmaf(a1, bv.w, acc[1][3]);
        }
        __syncthreads();
    }

    #pragma unroll
    for (int m = 0; m < 2; m++) {
        int row = ty * 2 + m;
        float4 v;
        v.x = fmaxf(acc[m][0], 0.f);
        v.y = fmaxf(acc[m][1], 0.f);
        v.z = fmaxf(acc[m][2], 0.f);
        v.w = fmaxf(acc[m][3], 0.f);
        *(float4*)&O[row * Dn + n0 + tx * 4] = v;
    }
}

// ---------------------------------------------------------------------------
// final = stim_out + LN(rec_out) * g + b ; writes d_out rows [0,32)
// ---------------------------------------------------------------------------
__global__ __launch_bounds__(256) void ln_final_kernel(
    const float* __restrict__ gamma, const float* __restrict__ beta,
    float* __restrict__ out)
{
    const int row = blockIdx.x;
    const float* rec = g_act[1] + row * Dn;
    const float* stm = g_act[0] + row * Dn;
    float s = 0.f, ss = 0.f;
    for (int i = threadIdx.x; i < Dn; i += 256) {
        float v = rec[i]; s += v; ss += v * v;
    }
    __shared__ float rs[256], rq[256];
    rs[threadIdx.x] = s; rq[threadIdx.x] = ss;
    __syncthreads();
    for (int off = 128; off > 0; off >>= 1) {
        if (threadIdx.x < off) {
            rs[threadIdx.x] += rs[threadIdx.x + off];
            rq[threadIdx.x] += rq[threadIdx.x + off];
        }
        __syncthreads();
    }
    float mean = rs[0] * (1.f / Dn);
    float var  = rq[0] * (1.f / Dn) - mean * mean;
    float inv  = rsqrtf(var + 1e-5f);
    for (int i = threadIdx.x; i < Dn; i += 256)
        out[row * Dn + i] = (rec[i] - mean) * inv * gamma[i] + beta[i] + stm[i];
}

// ---------------------------------------------------------------------------
// Small MLP GEMM: O[b,n] = X[b,:] . W[:,n] + bias[n]
// M=32 fixed, BN=64, BK=32, 256 threads, thread 2x4.
// insel: 0=external ptr (final in d_out), 1=g_h1, 2=g_h2
// outsel: 1=g_h1, 2=g_h2, 3=g_o
// ---------------------------------------------------------------------------
__global__ __launch_bounds__(256) void mlp_gemm(
    const float* __restrict__ xext, int insel,
    const float* __restrict__ W, const float* __restrict__ bias,
    int K, int N, int outsel)
{
    const float* __restrict__ X = (insel == 0) ? xext : (insel == 1 ? g_h1 : g_h2);
    float* __restrict__ O = (outsel == 1) ? g_h1 : (outsel == 2 ? g_h2 : g_o);
    const int n0 = blockIdx.x * 64;

    __shared__ float Xs[32][33];
    __shared__ float Ws[32][64];

    const int tid = threadIdx.x;
    const int tx = tid & 15;
    const int ty = tid >> 4;
    const int bld = tid >> 5;
    const int kld = tid & 31;
    const int kw  = tid >> 4;
    const int nw  = (tid & 15) << 2;

    float acc[2][4] = {};

    for (int k0 = 0; k0 < K; k0 += 32) {
        #pragma unroll
        for (int r = 0; r < 4; r++)
            Xs[kld][bld + 8 * r] = X[(bld + 8 * r) * K + k0 + kld];
        #pragma unroll
        for (int r = 0; r < 2; r++)
            *(float4*)&Ws[kw + 16 * r][nw] =
                *(const float4*)&W[(size_t)(k0 + kw + 16 * r) * N + n0 + nw];
        __syncthreads();

        #pragma unroll
        for (int kk = 0; kk < 32; kk++) {
            float a0 = Xs[kk][ty * 2 + 0];
            float a1 = Xs[kk][ty * 2 + 1];
            float4 bv = *(const float4*)&Ws[kk][tx * 4];
            acc[0][0] = fmaf(a0, bv.x, acc[0][0]);
            acc[0][1] = fmaf(a0, bv.y, acc[0][1]);
            acc[0][2] = fmaf(a0, bv.z, acc[0][2]);
            acc[0][3] = fmaf(a0, bv.w, acc[0][3]);
            acc[1][0] = fmaf(a1, bv.x, acc[1][0]);
            acc[1][1] = fmaf(a1, bv.y, acc[1][1]);
            acc[1][2] = fmaf(a1, bv.z, acc[1][2]);
            acc[1][3] = fmaf(a1, bv.w, acc[1][3]);
        }
        __syncthreads();
    }

    float4 bi = *(const float4*)&bias[n0 + tx * 4];
    #pragma unroll
    for (int m = 0; m < 2; m++) {
        int row = ty * 2 + m;
        float4 v;
        v.x = acc[m][0] + bi.x;
        v.y = acc[m][1] + bi.y;
        v.z = acc[m][2] + bi.z;
        v.w = acc[m][3] + bi.w;
        *(float4*)&O[row * N + n0 + tx * 4] = v;
    }
}

// ---------------------------------------------------------------------------
// In-place per-row LayerNorm + activation. act: 1=relu, 2=tanh
// sel: 1=g_h1(512), 2=g_h2(256), 3=g_o(64)
// ---------------------------------------------------------------------------
__global__ __launch_bounds__(256) void lnact_kernel(
    int sel, const float* __restrict__ gamma, const float* __restrict__ beta,
    int Nw, int act)
{
    float* base = (sel == 1) ? g_h1 : (sel == 2 ? g_h2 : g_o);
    float* p = base + blockIdx.x * Nw;
    float s = 0.f, ss = 0.f;
    for (int i = threadIdx.x; i < Nw; i += 256) {
        float v = p[i]; s += v; ss += v * v;
    }
    __shared__ float rs[256], rq[256];
    rs[threadIdx.x] = s; rq[threadIdx.x] = ss;
    __syncthreads();
    for (int off = 128; off > 0; off >>= 1) {
        if (threadIdx.x < off) {
            rs[threadIdx.x] += rs[threadIdx.x + off];
            rq[threadIdx.x] += rq[threadIdx.x + off];
        }
        __syncthreads();
    }
    float mean = rs[0] / (float)Nw;
    float var  = rq[0] / (float)Nw - mean * mean;
    float inv  = rsqrtf(var + 1e-5f);
    for (int i = threadIdx.x; i < Nw; i += 256) {
        float v = (p[i] - mean) * inv * gamma[i] + beta[i];
        v = (act == 1) ? fmaxf(v, 0.f) : tanhf(v);
        p[i] = v;
    }
}

// ---------------------------------------------------------------------------
// dop = mean_b(g_o) * ALPHA_SCALE ; alpha[d] = dop[d/64]
// ---------------------------------------------------------------------------
__global__ __launch_bounds__(256) void alpha_kernel()
{
    __shared__ float dsh[Un];
    int t = threadIdx.x;
    if (t < Un) {
        float s = 0.f;
        #pragma unroll
        for (int b = 0; b < Bn; b++) s += g_o[b * Un + t];
        dsh[t] = s * (9.9f / (float)Bn);
    }
    __syncthreads();
    for (int d = t; d < Dn; d += 256) g_alpha[d] = dsh[d >> 6];
}

// ---------------------------------------------------------------------------
// Update GEMM (K=32): V[i,j] = (W[i,j] + (sum_b A[b,i]*C[b,j]) * alpha[j]) * (1-decay[i])
// Writes V into d_out; emits per-block row sumsq partials into g_part.
// grid (64 j-blocks, 64 i-blocks, 2 matrices), 256 threads, thread 4x4.
// ---------------------------------------------------------------------------
__global__ __launch_bounds__(256) void update_kernel(
    const float* __restrict__ stim, const float* __restrict__ prev,
    const float* __restrict__ Wh, const float* __restrict__ Wr,
    const float* __restrict__ decay, float* __restrict__ out)
{
    const int mat = blockIdx.z;
    const float* __restrict__ A = mat ? prev : stim;
    const float* __restrict__ C = g_act[mat];
    const float* __restrict__ W = mat ? Wr : Wh;
    float* __restrict__ O = out + (size_t)(Bn + mat * Dn) * Dn;
    const int i0 = blockIdx.y * 64;
    const int j0 = blockIdx.x * 64;

    __shared__ float As[32][64];
    __shared__ float Cs[32][64];
    __shared__ float red[64][17];

    const int tid = threadIdx.x;
    for (int idx = tid; idx < 32 * 64; idx += 256) {
        int b = idx >> 6, c = idx & 63;
        As[b][c] = A[b * Dn + i0 + c];
        Cs[b][c] = C[b * Dn + j0 + c];
    }
    __syncthreads();

    const int tx = tid & 15;
    const int ty = tid >> 4;
    float acc[4][4] = {};

    #pragma unroll
    for (int b = 0; b < 32; b++) {
        float4 a4 = *(const float4*)&As[b][ty * 4];
        float4 c4 = *(const float4*)&Cs[b][tx * 4];
        float av[4] = {a4.x, a4.y, a4.z, a4.w};
        float cv[4] = {c4.x, c4.y, c4.z, c4.w};
        #pragma unroll
        for (int m = 0; m < 4; m++)
            #pragma unroll
            for (int n = 0; n < 4; n++)
                acc[m][n] = fmaf(av[m], cv[n], acc[m][n]);
    }

    float4 al = *(const float4*)&g_alpha[j0 + tx * 4];
    float alv[4] = {al.x, al.y, al.z, al.w};

    #pragma unroll
    for (int m = 0; m < 4; m++) {
        int i = i0 + ty * 4 + m;
        float dm = 1.0f - decay[i];
        float4 w4 = *(const float4*)&W[(size_t)i * Dn + j0 + tx * 4];
        float wv[4] = {w4.x, w4.y, w4.z, w4.w};
        float v[4], ssum = 0.f;
        #pragma unroll
        for (int n = 0; n < 4; n++) {
            v[n] = (wv[n] + acc[m][n] * alv[n]) * dm;
            ssum = fmaf(v[n], v[n], ssum);
        }
        float4 o4 = {v[0], v[1], v[2], v[3]};
        *(float4*)&O[(size_t)i * Dn + j0 + tx * 4] = o4;
        red[ty * 4 + m][tx] = ssum;
    }
    __syncthreads();

    if (tid < 64) {
        float s = 0.f;
        #pragma unroll
        for (int t = 0; t < 16; t++) s += red[tid][t];
        g_part[mat][blockIdx.x][i0 + tid] = s;   // deterministic partial
    }
}

// ---------------------------------------------------------------------------
// g_norm[mat][i] = sum over 64 j-blocks of partials
// ---------------------------------------------------------------------------
__global__ __launch_bounds__(256) void norm_reduce_kernel()
{
    int mat = blockIdx.y;
    int i = blockIdx.x * 256 + threadIdx.x;
    float s = 0.f;
    #pragma unroll 8
    for (int jb = 0; jb < 64; jb++) s += g_part[mat][jb][i];
    g_norm[mat][i] = s;
}

// ---------------------------------------------------------------------------
// In-place row L2 normalize of the two D x D blocks of d_out.
// ---------------------------------------------------------------------------
__global__ __launch_bounds__(256) void scale_kernel(float* __restrict__ out)
{
    size_t idx = (size_t)blockIdx.x * 256 + threadIdx.x;     // float4 index
    const size_t total4 = (size_t)2 * Dn * Dn / 4;
    if (idx >= total4) return;
    size_t e = idx << 2;
    int mat = (int)(e >> 24);            // D*D = 2^24
    int i = (int)((e >> 12) & (Dn - 1)); // row within matrix
    float n = g_norm[mat][i];
    float sc = 1.0f / fmaxf(sqrtf(n), 1e-12f);
    float4* p = (float4*)(out + (size_t)Bn * Dn) + idx;
    float4 v = *p;
    v.x *= sc; v.y *= sc; v.z *= sc; v.w *= sc;
    *p = v;
}

// ---------------------------------------------------------------------------
extern "C" void kernel_launch(void* const* d_in, const int* in_sizes, int n_in,
                              void* d_out, int out_size)
{
    const float* stimulus = (const float*)d_in[0];
    const float* prev_act = (const float*)d_in[1];
    const float* W_heb    = (const float*)d_in[2];
    const float* W_rec    = (const float*)d_in[3];
    const float* decay    = (const float*)d_in[4];
    const float* ln_rec_g = (const float*)d_in[5];
    const float* ln_rec_b = (const float*)d_in[6];
    const float* fc1_w    = (const float*)d_in[7];
    const float* fc1_b    = (const float*)d_in[8];
    const float* ln1_g    = (const float*)d_in[9];
    const float* ln1_b    = (const float*)d_in[10];
    const float* fc2_w    = (const float*)d_in[11];
    const float* fc2_b    = (const float*)d_in[12];
    const float* ln2_g    = (const float*)d_in[13];
    const float* ln2_b    = (const float*)d_in[14];
    const float* fc3_w    = (const float*)d_in[15];
    const float* fc3_b    = (const float*)d_in[16];
    const float* lno_g    = (const float*)d_in[17];
    const float* lno_b    = (const float*)d_in[18];
    float* out = (float*)d_out;

    // 1. forward GEMMs (relu), both matrices
    fwd_gemm<<<dim3(64, 2, 1), 256>>>(stimulus, prev_act, W_heb, W_rec);
    // 2. final = stim_out + LN(rec_out)  -> d_out rows [0,32)
    ln_final_kernel<<<32, 256>>>(ln_rec_g, ln_rec_b, out);
    // 3-8. neuromodulator MLP
    mlp_gemm<<<dim3(8, 1, 1), 256>>>(out, 0, fc1_w, fc1_b, 4096, 512, 1);
    lnact_kernel<<<32, 256>>>(1, ln1_g, ln1_b, 512, 1);
    mlp_gemm<<<dim3(4, 1, 1), 256>>>(nullptr, 1, fc2_w, fc2_b, 512, 256, 2);
    lnact_kernel<<<32, 256>>>(2, ln2_g, ln2_b, 256, 1);
    mlp_gemm<<<dim3(1, 1, 1), 256>>>(nullptr, 2, fc3_w, fc3_b, 256, 64, 3);
    lnact_kernel<<<32, 256>>>(3, lno_g, lno_b, 64, 2);
    // 9. dopamine -> alpha
    alpha_kernel<<<1, 256>>>();
    // 10. Hebbian updates fused with decay + row-sumsq partials
    update_kernel<<<dim3(64, 64, 2), 256>>>(stimulus, prev_act, W_heb, W_rec, decay, out);
    // 11. row norms
    norm_reduce_kernel<<<dim3(16, 2, 1), 256>>>();
    // 12. in-place row L2 normalize
    scale_kernel<<<(unsigned)(((size_t)2 * Dn * Dn / 4 + 255) / 256), 256>>>(out);
}

// round 2
// speedup vs baseline: 2.4921x; 2.4921x over previous
#include <cuda_runtime.h>
#include <math.h>

#define Dn 4096
#define Bn 32
#define Un 64

// ---------------- scratch (__device__ globals; no allocation) ----------------
__device__ float g_fpart[8][2][Bn][Dn];   // fwd split-K partials (8 MB)
__device__ float g_act[2][Bn * Dn];       // [0]=stim_out, [1]=rec_out (post-relu)
__device__ float g_mp1[16][Bn][512];      // fc1 partials
__device__ float g_mp2[8][Bn][256];       // fc2 partials
__device__ float g_mp3[8][Bn][64];        // fc3 partials
__device__ float g_h1[Bn * 512];
__device__ float g_h2[Bn * 256];
__device__ float g_o[Bn * Un];
__device__ float g_alpha[Dn];
__device__ float g_norm[2][Dn];
__device__ float g_part[2][64][Dn];       // per-(matrix, j-block) row sumsq partials

// ---------------------------------------------------------------------------
// Forward GEMM v2: partial[split][mat] = X[32,4096] @ W[:,n-block] over K-chunk
// BM=32, BN=128, BK=32, Kc=512 (8 splits). 256 threads, 4x4 micro-tile.
// Register-staged double buffering hides LDG latency.
// ---------------------------------------------------------------------------
__global__ __launch_bounds__(256) void fwd_gemm2(
    const float* __restrict__ stim, const float* __restrict__ prev,
    const float* __restrict__ Wh, const float* __restrict__ Wr)
{
    const int mat = blockIdx.z;
    const float* __restrict__ X = mat ? prev : stim;
    const float* __restrict__ W = mat ? Wr : Wh;
    const int n0 = blockIdx.x * 128;
    const int kbase = blockIdx.y * 512;

    __shared__ float Xs[32][36];    // [k][m], pad 36 keeps LDS.128 16B-aligned
    __shared__ float Ws[32][128];   // [k][n]

    const int tid = threadIdx.x;
    const int xrow = tid >> 3;            // 0..31
    const int xk   = (tid & 7) << 2;      // 0..28 step 4
    const int wk   = tid >> 5;            // 0..7
    const int wn   = (tid & 31) << 2;     // 0..124 step 4
    const int tx   = tid & 31;            // n-group (4 cols)
    const int ty   = tid >> 5;            // m-group (4 rows)

    float4 xr  = *(const float4*)&X[xrow * Dn + kbase + xk];
    float4 wr0 = *(const float4*)&W[(size_t)(kbase + wk +  0) * Dn + n0 + wn];
    float4 wr1 = *(const float4*)&W[(size_t)(kbase + wk +  8) * Dn + n0 + wn];
    float4 wr2 = *(const float4*)&W[(size_t)(kbase + wk + 16) * Dn + n0 + wn];
    float4 wr3 = *(const float4*)&W[(size_t)(kbase + wk + 24) * Dn + n0 + wn];

    float acc[4][4] = {};

    for (int c = 0; c < 16; ++c) {
        Xs[xk + 0][xrow] = xr.x;
        Xs[xk + 1][xrow] = xr.y;
        Xs[xk + 2][xrow] = xr.z;
        Xs[xk + 3][xrow] = xr.w;
        *(float4*)&Ws[wk +  0][wn] = wr0;
        *(float4*)&Ws[wk +  8][wn] = wr1;
        *(float4*)&Ws[wk + 16][wn] = wr2;
        *(float4*)&Ws[wk + 24][wn] = wr3;
        __syncthreads();
        if (c < 15) {
            int k = kbase + (c + 1) * 32;
            xr  = *(const float4*)&X[xrow * Dn + k + xk];
            wr0 = *(const float4*)&W[(size_t)(k + wk +  0) * Dn + n0 + wn];
            wr1 = *(const float4*)&W[(size_t)(k + wk +  8) * Dn + n0 + wn];
            wr2 = *(const float4*)&W[(size_t)(k + wk + 16) * Dn + n0 + wn];
            wr3 = *(const float4*)&W[(size_t)(k + wk + 24) * Dn + n0 + wn];
        }
        #pragma unroll 8
        for (int kk = 0; kk < 32; ++kk) {
            float4 a = *(const float4*)&Xs[kk][ty << 2];
            float4 b = *(const float4*)&Ws[kk][tx << 2];
            acc[0][0] = fmaf(a.x, b.x, acc[0][0]);
            acc[0][1] = fmaf(a.x, b.y, acc[0][1]);
            acc[0][2] = fmaf(a.x, b.z, acc[0][2]);
            acc[0][3] = fmaf(a.x, b.w, acc[0][3]);
            acc[1][0] = fmaf(a.y, b.x, acc[1][0]);
            acc[1][1] = fmaf(a.y, b.y, acc[1][1]);
            acc[1][2] = fmaf(a.y, b.z, acc[1][2]);
            acc[1][3] = fmaf(a.y, b.w, acc[1][3]);
            acc[2][0] = fmaf(a.z, b.x, acc[2][0]);
            acc[2][1] = fmaf(a.z, b.y, acc[2][1]);
            acc[2][2] = fmaf(a.z, b.z, acc[2][2]);
            acc[2][3] = fmaf(a.z, b.w, acc[2][3]);
            acc[3][0] = fmaf(a.w, b.x, acc[3][0]);
            acc[3][1] = fmaf(a.w, b.y, acc[3][1]);
            acc[3][2] = fmaf(a.w, b.z, acc[3][2]);
            acc[3][3] = fmaf(a.w, b.w, acc[3][3]);
        }
        __syncthreads();
    }

    float* P = &g_fpart[blockIdx.y][mat][0][0];
    #pragma unroll
    for (int m = 0; m < 4; ++m) {
        int row = (ty << 2) + m;
        float4 v = make_float4(acc[m][0], acc[m][1], acc[m][2], acc[m][3]);
        *(float4*)&P[row * Dn + n0 + (tx << 2)] = v;
    }
}

// ---------------------------------------------------------------------------
// g_act[mat] = relu(sum over 8 splits of g_fpart)
// ---------------------------------------------------------------------------
__global__ __launch_bounds__(256) void reduce_relu_kernel()
{
    int f = blockIdx.x * 256 + threadIdx.x;   // float4 index, 65536 total
    const float4* p = (const float4*)&g_fpart[0][0][0][0];
    float4 a = p[f];
    #pragma unroll
    for (int s = 1; s < 8; ++s) {
        float4 b = p[s * 65536 + f];
        a.x += b.x; a.y += b.y; a.z += b.z; a.w += b.w;
    }
    a.x = fmaxf(a.x, 0.f); a.y = fmaxf(a.y, 0.f);
    a.z = fmaxf(a.z, 0.f); a.w = fmaxf(a.w, 0.f);
    ((float4*)&g_act[0][0])[f] = a;
}

// ---------------------------------------------------------------------------
// final = stim_out + LN(rec_out) * g + b ; writes d_out rows [0,32)
// ---------------------------------------------------------------------------
__global__ __launch_bounds__(256) void ln_final_kernel(
    const float* __restrict__ gamma, const float* __restrict__ beta,
    float* __restrict__ out)
{
    const int row = blockIdx.x;
    const float* rec = g_act[1] + row * Dn;
    const float* stm = g_act[0] + row * Dn;
    float s = 0.f, ss = 0.f;
    for (int i = threadIdx.x; i < Dn; i += 256) {
        float v = rec[i]; s += v; ss += v * v;
    }
    __shared__ float rs[256], rq[256];
    rs[threadIdx.x] = s; rq[threadIdx.x] = ss;
    __syncthreads();
    for (int off = 128; off > 0; off >>= 1) {
        if (threadIdx.x < off) {
            rs[threadIdx.x] += rs[threadIdx.x + off];
            rq[threadIdx.x] += rq[threadIdx.x + off];
        }
        __syncthreads();
    }
    float mean = rs[0] * (1.f / Dn);
    float var  = rq[0] * (1.f / Dn) - mean * mean;
    float inv  = rsqrtf(var + 1e-5f);
    for (int i = threadIdx.x; i < Dn; i += 256)
        out[row * Dn + i] = (rec[i] - mean) * inv * gamma[i] + beta[i] + stm[i];
}

// ---------------------------------------------------------------------------
// MLP GEMM v2 (split-K, BN=128): partial[split] = X[32,K-chunk] @ W-chunk
// insel: 0 = external pointer (final in d_out), 1 = g_h1
// psel:  1 = g_mp1, 2 = g_mp2
// ---------------------------------------------------------------------------
__global__ __launch_bounds__(256) void mlp_gemm2(
    const float* __restrict__ xext, int insel,
    const float* __restrict__ W, int K, int N, int Kc, int psel)
{
    const float* __restrict__ X = (insel == 0) ? xext : g_h1;
    float* __restrict__ P = (psel == 1) ? &g_mp1[0][0][0] : &g_mp2[0][0][0];
    const int n0 = blockIdx.x * 128;
    const int kbase = blockIdx.y * Kc;
    const int iters = Kc >> 5;

    __shared__ float Xs[32][36];
    __shared__ float Ws[32][128];

    const int tid = threadIdx.x;
    const int xrow = tid >> 3;
    const int xk   = (tid & 7) << 2;
    const int wk   = tid >> 5;
    const int wn   = (tid & 31) << 2;
    const int tx   = tid & 31;
    const int ty   = tid >> 5;

    float4 xr  = *(const float4*)&X[xrow * K + kbase + xk];
    float4 wr0 = *(const float4*)&W[(size_t)(kbase + wk +  0) * N + n0 + wn];
    float4 wr1 = *(const float4*)&W[(size_t)(kbase + wk +  8) * N + n0 + wn];
    float4 wr2 = *(const float4*)&W[(size_t)(kbase + wk + 16) * N + n0 + wn];
    float4 wr3 = *(const float4*)&W[(size_t)(kbase + wk + 24) * N + n0 + wn];

    float acc[4][4] = {};

    for (int c = 0; c < iters; ++c) {
        Xs[xk + 0][xrow] = xr.x;
        Xs[xk + 1][xrow] = xr.y;
        Xs[xk + 2][xrow] = xr.z;
        Xs[xk + 3][xrow] = xr.w;
        *(float4*)&Ws[wk +  0][wn] = wr0;
        *(float4*)&Ws[wk +  8][wn] = wr1;
        *(float4*)&Ws[wk + 16][wn] = wr2;
        *(float4*)&Ws[wk + 24][wn] = wr3;
        __syncthreads();
        if (c + 1 < iters) {
            int k = kbase + (c + 1) * 32;
            xr  = *(const float4*)&X[xrow * K + k + xk];
            wr0 = *(const float4*)&W[(size_t)(k + wk +  0) * N + n0 + wn];
            wr1 = *(const float4*)&W[(size_t)(k + wk +  8) * N + n0 + wn];
            wr2 = *(const float4*)&W[(size_t)(k + wk + 16) * N + n0 + wn];
            wr3 = *(const float4*)&W[(size_t)(k + wk + 24) * N + n0 + wn];
        }
        #pragma unroll 8
        for (int kk = 0; kk < 32; ++kk) {
            float4 a = *(const float4*)&Xs[kk][ty << 2];
            float4 b = *(const float4*)&Ws[kk][tx << 2];
            acc[0][0] = fmaf(a.x, b.x, acc[0][0]);
            acc[0][1] = fmaf(a.x, b.y, acc[0][1]);
            acc[0][2] = fmaf(a.x, b.z, acc[0][2]);
            acc[0][3] = fmaf(a.x, b.w, acc[0][3]);
            acc[1][0] = fmaf(a.y, b.x, acc[1][0]);
            acc[1][1] = fmaf(a.y, b.y, acc[1][1]);
            acc[1][2] = fmaf(a.y, b.z, acc[1][2]);
            acc[1][3] = fmaf(a.y, b.w, acc[1][3]);
            acc[2][0] = fmaf(a.z, b.x, acc[2][0]);
            acc[2][1] = fmaf(a.z, b.y, acc[2][1]);
            acc[2][2] = fmaf(a.z, b.z, acc[2][2]);
            acc[2][3] = fmaf(a.z, b.w, acc[2][3]);
            acc[3][0] = fmaf(a.w, b.x, acc[3][0]);
            acc[3][1] = fmaf(a.w, b.y, acc[3][1]);
            acc[3][2] = fmaf(a.w, b.z, acc[3][2]);
            acc[3][3] = fmaf(a.w, b.w, acc[3][3]);
        }
        __syncthreads();
    }

    #pragma unroll
    for (int m = 0; m < 4; ++m) {
        int row = (ty << 2) + m;
        float4 v = make_float4(acc[m][0], acc[m][1], acc[m][2], acc[m][3]);
        *(float4*)&P[((size_t)blockIdx.y * Bn + row) * N + n0 + (tx << 2)] = v;
    }
}

// ---------------------------------------------------------------------------
// fc3: g_mp3[split] = g_h2[32,256-chunk] @ fc3_w-chunk   (N=64, Kc=32, 8 splits)
// ---------------------------------------------------------------------------
__global__ __launch_bounds__(256) void fc3_gemm(const float* __restrict__ W)
{
    const int kb = blockIdx.x * 32;
    __shared__ float Xs[32][33];
    __shared__ float Ws[32][64];
    const int tid = threadIdx.x;
    const int xrow = tid >> 3, xk = (tid & 7) << 2;
    const int kw = tid >> 4, wn = (tid & 15) << 2;

    float4 xv = *(const float4*)&g_h2[xrow * 256 + kb + xk];
    Xs[xk + 0][xrow] = xv.x;
    Xs[xk + 1][xrow] = xv.y;
    Xs[xk + 2][xrow] = xv.z;
    Xs[xk + 3][xrow] = xv.w;
    *(float4*)&Ws[kw +  0][wn] = *(const float4*)&W[(kb + kw +  0) * 64 + wn];
    *(float4*)&Ws[kw + 16][wn] = *(const float4*)&W[(kb + kw + 16) * 64 + wn];
    __syncthreads();

    const int tx = tid & 15, ty = tid >> 4;
    float acc[2][4] = {};
    #pragma unroll 8
    for (int kk = 0; kk < 32; ++kk) {
        float a0 = Xs[kk][ty * 2 + 0];
        float a1 = Xs[kk][ty * 2 + 1];
        float4 b = *(const float4*)&Ws[kk][tx << 2];
        acc[0][0] = fmaf(a0, b.x, acc[0][0]);
        acc[0][1] = fmaf(a0, b.y, acc[0][1]);
        acc[0][2] = fmaf(a0, b.z, acc[0][2]);
        acc[0][3] = fmaf(a0, b.w, acc[0][3]);
        acc[1][0] = fmaf(a1, b.x, acc[1][0]);
        acc[1][1] = fmaf(a1, b.y, acc[1][1]);
        acc[1][2] = fmaf(a1, b.z, acc[1][2]);
        acc[1][3] = fmaf(a1, b.w, acc[1][3]);
    }
    #pragma unroll
    for (int m = 0; m < 2; ++m) {
        int row = ty * 2 + m;
        float4 v = make_float4(acc[m][0], acc[m][1], acc[m][2], acc[m][3]);
        *(float4*)&g_mp3[blockIdx.x][row][tx << 2] = v;
        // fix row index below (written via pointer math to keep float4 store)
        *(float4*)((float*)&g_mp3[blockIdx.x][0][0] + row * 64 + (tx << 2)) = v;
    }
}

// ---------------------------------------------------------------------------
// Split-reduce + bias + LayerNorm + activation. act: 1=relu, 2=tanh
// psel: 1=(g_mp1,S=16,N=512)->g_h1, 2=(g_mp2,S=8,N=256)->g_h2, 3=(g_mp3,S=8,N=64)->g_o
// ---------------------------------------------------------------------------
__global__ __launch_bounds__(256) void lnact_reduce(
    int psel, int S, int N,
    const float* __restrict__ bias,
    const float* __restrict__ gamma, const float* __restrict__ beta,
    int act)
{
    const float* part = (psel == 1) ? &g_mp1[0][0][0]
                      : (psel == 2) ? &g_mp2[0][0][0] : &g_mp3[0][0][0];
    float* outb = (psel == 1) ? g_h1 : (psel == 2) ? g_h2 : g_o;
    const int row = blockIdx.x;

    __shared__ float vbuf[512];
    float s = 0.f, ss = 0.f;
    for (int i = threadIdx.x; i < N; i += 256) {
        float v = bias[i];
        for (int sp = 0; sp < S; ++sp)
            v += part[((size_t)sp * Bn + row) * N + i];
        vbuf[i] = v;
        s += v; ss += v * v;
    }
    __shared__ float rs[256], rq[256];
    rs[threadIdx.x] = s; rq[threadIdx.x] = ss;
    __syncthreads();
    for (int off = 128; off > 0; off >>= 1) {
        if (threadIdx.x < off) {
            rs[threadIdx.x] += rs[threadIdx.x + off];
            rq[threadIdx.x] += rq[threadIdx.x + off];
        }
        __syncthreads();
    }
    float mean = rs[0] / (float)N;
    float var  = rq[0] / (float)N - mean * mean;
    float inv  = rsqrtf(var + 1e-5f);
    for (int i = threadIdx.x; i < N; i += 256) {
        float v = (vbuf[i] - mean) * inv * gamma[i] + beta[i];
        v = (act == 1) ? fmaxf(v, 0.f) : tanhf(v);
        outb[row * N + i] = v;
    }
}

// ---------------------------------------------------------------------------
// dop = mean_b(g_o) * ALPHA_SCALE ; alpha[d] = dop[d/64]
// ---------------------------------------------------------------------------
__global__ __launch_bounds__(256) void alpha_kernel()
{
    __shared__ float dsh[Un];
    int t = threadIdx.x;
    if (t < Un) {
        float s = 0.f;
        #pragma unroll
        for (int b = 0; b < Bn; b++) s += g_o[b * Un + t];
        dsh[t] = s * (9.9f / (float)Bn);
    }
    __syncthreads();
    for (int d = t; d < Dn; d += 256) g_alpha[d] = dsh[d >> 6];
}

// ---------------------------------------------------------------------------
// Update GEMM (K=32): V[i,j] = (W[i,j] + (sum_b A[b,i]*C[b,j]) * alpha[j]) * (1-decay[i])
// Writes V into d_out; emits per-block row sumsq partials into g_part.
// ---------------------------------------------------------------------------
__global__ __launch_bounds__(256) void update_kernel(
    const float* __restrict__ stim, const float* __restrict__ prev,
    const float* __restrict__ Wh, const float* __restrict__ Wr,
    const float* __restrict__ decay, float* __restrict__ out)
{
    const int mat = blockIdx.z;
    const float* __restrict__ A = mat ? prev : stim;
    const float* __restrict__ C = g_act[mat];
    const float* __restrict__ W = mat ? Wr : Wh;
    float* __restrict__ O = out + (size_t)(Bn + mat * Dn) * Dn;
    const int i0 = blockIdx.y * 64;
    const int j0 = blockIdx.x * 64;

    __shared__ float As[32][64];
    __shared__ float Cs[32][64];
    __shared__ float red[64][17];

    const int tid = threadIdx.x;
    for (int idx = tid; idx < 32 * 64; idx += 256) {
        int b = idx >> 6, c = idx & 63;
        As[b][c] = A[b * Dn + i0 + c];
        Cs[b][c] = C[b * Dn + j0 + c];
    }
    __syncthreads();

    const int tx = tid & 15;
    const int ty = tid >> 4;
    float acc[4][4] = {};

    #pragma unroll
    for (int b = 0; b < 32; b++) {
        float4 a4 = *(const float4*)&As[b][ty * 4];
        float4 c4 = *(const float4*)&Cs[b][tx * 4];
        float av[4] = {a4.x, a4.y, a4.z, a4.w};
        float cv[4] = {c4.x, c4.y, c4.z, c4.w};
        #pragma unroll
        for (int m = 0; m < 4; m++)
            #pragma unroll
            for (int n = 0; n < 4; n++)
                acc[m][n] = fmaf(av[m], cv[n], acc[m][n]);
    }

    float4 al = *(const float4*)&g_alpha[j0 + tx * 4];
    float alv[4] = {al.x, al.y, al.z, al.w};

    #pragma unroll
    for (int m = 0; m < 4; m++) {
        int i = i0 + ty * 4 + m;
        float dm = 1.0f - decay[i];
        float4 w4 = *(const float4*)&W[(size_t)i * Dn + j0 + tx * 4];
        float wv[4] = {w4.x, w4.y, w4.z, w4.w};
        float v[4], ssum = 0.f;
        #pragma unroll
        for (int n = 0; n < 4; n++) {
            v[n] = (wv[n] + acc[m][n] * alv[n]) * dm;
            ssum = fmaf(v[n], v[n], ssum);
        }
        float4 o4 = {v[0], v[1], v[2], v[3]};
        *(float4*)&O[(size_t)i * Dn + j0 + tx * 4] = o4;
        red[ty * 4 + m][tx] = ssum;
    }
    __syncthreads();

    if (tid < 64) {
        float s = 0.f;
        #pragma unroll
        for (int t = 0; t < 16; t++) s += red[tid][t];
        g_part[mat][blockIdx.x][i0 + tid] = s;
    }
}

// ---------------------------------------------------------------------------
__global__ __launch_bounds__(256) void norm_reduce_kernel()
{
    int mat = blockIdx.y;
    int i = blockIdx.x * 256 + threadIdx.x;
    float s = 0.f;
    #pragma unroll 8
    for (int jb = 0; jb < 64; jb++) s += g_part[mat][jb][i];
    g_norm[mat][i] = s;
}

// ---------------------------------------------------------------------------
// In-place row L2 normalize of the two D x D blocks of d_out. 4 float4/thread.
// ---------------------------------------------------------------------------
__global__ __launch_bounds__(256) void scale_kernel(float* __restrict__ out)
{
    float4* base = (float4*)(out + (size_t)Bn * Dn);
    int t0 = blockIdx.x * 1024 + threadIdx.x;
    #pragma unroll
    for (int r = 0; r < 4; r++) {
        int idx = t0 + r * 256;
        size_t e = (size_t)idx << 2;
        int mat = (int)(e >> 24);            // D*D = 2^24
        int i = (int)((e >> 12) & (Dn - 1)); // row within matrix
        float n = g_norm[mat][i];
        float sc = 1.0f / fmaxf(sqrtf(n), 1e-12f);
        float4 v = base[idx];
        v.x *= sc; v.y *= sc; v.z *= sc; v.w *= sc;
        base[idx] = v;
    }
}

// ---------------------------------------------------------------------------
extern "C" void kernel_launch(void* const* d_in, const int* in_sizes, int n_in,
                              void* d_out, int out_size)
{
    const float* stimulus = (const float*)d_in[0];
    const float* prev_act = (const float*)d_in[1];
    const float* W_heb    = (const float*)d_in[2];
    const float* W_rec    = (const float*)d_in[3];
    const float* decay    = (const float*)d_in[4];
    const float* ln_rec_g = (const float*)d_in[5];
    const float* ln_rec_b = (const float*)d_in[6];
    const float* fc1_w    = (const float*)d_in[7];
    const float* fc1_b    = (const float*)d_in[8];
    const float* ln1_g    = (const float*)d_in[9];
    const float* ln1_b    = (const float*)d_in[10];
    const float* fc2_w    = (const float*)d_in[11];
    const float* fc2_b    = (const float*)d_in[12];
    const float* ln2_g    = (const float*)d_in[13];
    const float* ln2_b    = (const float*)d_in[14];
    const float* fc3_w    = (const float*)d_in[15];
    const float* fc3_b    = (const float*)d_in[16];
    const float* lno_g    = (const float*)d_in[17];
    const float* lno_b    = (const float*)d_in[18];
    float* out = (float*)d_out;

    // 1. forward GEMMs (split-K 8)
    fwd_gemm2<<<dim3(32, 8, 2), 256>>>(stimulus, prev_act, W_heb, W_rec);
    // 2. reduce partials + relu -> g_act
    reduce_relu_kernel<<<256, 256>>>();
    // 3. final = stim_out + LN(rec_out) -> d_out rows [0,32)
    ln_final_kernel<<<32, 256>>>(ln_rec_g, ln_rec_b, out);
    // 4-9. neuromodulator MLP (split-K everywhere)
    mlp_gemm2<<<dim3(4, 16), 256>>>(out, 0, fc1_w, 4096, 512, 256, 1);
    lnact_reduce<<<32, 256>>>(1, 16, 512, fc1_b, ln1_g, ln1_b, 1);
    mlp_gemm2<<<dim3(2, 8), 256>>>(nullptr, 1, fc2_w, 512, 256, 64, 2);
    lnact_reduce<<<32, 256>>>(2, 8, 256, fc2_b, ln2_g, ln2_b, 1);
    fc3_gemm<<<8, 256>>>(fc3_w);
    lnact_reduce<<<32, 256>>>(3, 8, 64, fc3_b, lno_g, lno_b, 2);
    // 10. dopamine -> alpha
    alpha_kernel<<<1, 256>>>();
    // 11. Hebbian updates fused with decay + row-sumsq partials
    update_kernel<<<dim3(64, 64, 2), 256>>>(stimulus, prev_act, W_heb, W_rec, decay, out);
    // 12. row norms
    norm_reduce_kernel<<<dim3(16, 2), 256>>>();
    // 13. in-place row L2 normalize
    scale_kernel<<<8192, 256>>>(out);
}